// round 6
// baseline (speedup 1.0000x reference)
#include <cuda_runtime.h>
#include <cuda_bf16.h>
#include <math.h>

#define BB 32
#define TT 64
#define BT 2048
#define HID 200
#define FEAT 6144
#define SPLITS 8

// -------------------- scratch (device globals; no allocs) --------------------
__device__ float g_xt  [BT * 3  * 1024];
__device__ float g_e1  [BT * 8  * 1024];
__device__ float g_e2  [BT * 16 * 256];
__device__ float g_e3  [BT * 32 * 64];
__device__ float g_d2  [BT * 16 * 256];
__device__ float g_d1  [BT * 8  * 1024];
__device__ float g_feat[BT * FEAT];
__device__ float g_h1  [BT * HID];
__device__ float g_h2  [BT * HID];
__device__ float g_part[SPLITS * BT * HID];

// -------------------- permute [B,C,H,W,T] -> [B*T,C,H,W] --------------------
__global__ void permute_kernel(const float* __restrict__ x, float* __restrict__ xt) {
    int bidx = blockIdx.x;
    int h = bidx & 31;
    int c = (bidx >> 5) % 3;
    int b = bidx / 96;
    __shared__ float s[32][65];
    const float* src = x + (size_t)(((b * 3 + c) * 32 + h) * 32) * 64;
    for (int i = threadIdx.x; i < 2048; i += blockDim.x) {
        int w = i >> 6, t = i & 63;
        s[w][t] = src[i];
    }
    __syncthreads();
    for (int i = threadIdx.x; i < 2048; i += blockDim.x) {
        int t = i >> 5, w = i & 31;
        xt[((size_t)((b * 64 + t) * 3 + c) << 10) + (h << 5) + w] = s[w][t];
    }
}

// -------------------- standard conv3x3 (+optional 2x2 maxpool, +ReLU) --------
// Halo-padded SMEM tiles (1-px zero border, conflict-free pitch); COUT_T=8 reuse.
template<int CA, int COUT, int COUT_T, int HS, int NBT, int NPIX, bool POOL, int PITCH>
__global__ void __launch_bounds__(256, 2)
conv_std_k(const float* __restrict__ inA, const float* __restrict__ wgt,
           const float* __restrict__ bias, float* __restrict__ out)
{
    constexpr int GP   = COUT / COUT_T;
    constexpr int PXT  = HS * HS / NPIX;
    constexpr int ROWS = HS + 2;
    constexpr int CSZ  = ROWS * PITCH;
    constexpr int ASZ  = CA * CSZ;
    constexpr int WSZ  = COUT * CA * 9;
    extern __shared__ float sm[];
    float* sW  = sm;                  // transposed weights [CA*9][COUT]
    float* sBi = sW + WSZ;
    float* sIn = sBi + COUT;

    const int tid = threadIdx.x, NT = blockDim.x;
    const int bt0 = blockIdx.x * NBT;

    for (int i = tid; i < WSZ; i += NT) {
        int co = i % COUT;
        int rest = i / COUT;
        int ci = rest / 9, kk = rest % 9;
        sW[i] = wgt[(co * CA + ci) * 9 + kk];
    }
    for (int i = tid; i < COUT; i += NT) sBi[i] = bias[i];

    for (int i = tid; i < NBT * ASZ; i += NT) {
        int nn = i / ASZ, r2 = i % ASZ;
        int c = r2 / CSZ, cell = r2 % CSZ;
        int row = cell / PITCH, col = cell % PITCH;
        int hh = row - 1, ww = col - 1;
        float v = 0.f;
        if (hh >= 0 && hh < HS && ww >= 0 && ww < HS) {
            if (POOL) {
                const float* s = inA + (size_t)((bt0 + nn) * CA + c) * (4 * HS * HS)
                                     + (2 * hh) * (2 * HS) + 2 * ww;
                v = fmaxf(fmaxf(s[0], s[1]), fmaxf(s[2 * HS], s[2 * HS + 1]));
            } else {
                v = inA[(size_t)((bt0 + nn) * CA + c) * (HS * HS) + hh * HS + ww];
            }
        }
        sIn[i] = v;
    }
    __syncthreads();

    const int n   = tid / (GP * PXT);
    const int r   = tid % (GP * PXT);
    const int cog = r / PXT;
    const int p   = r % PXT;
    const int h   = p / (HS / NPIX);
    const int w0  = (p % (HS / NPIX)) * NPIX;
    const float* sI = sIn + n * ASZ;

    float acc[COUT_T][NPIX];
    #pragma unroll
    for (int co = 0; co < COUT_T; co++) {
        float b = sBi[cog * COUT_T + co];
        #pragma unroll
        for (int j = 0; j < NPIX; j++) acc[co][j] = b;
    }

    #pragma unroll 1
    for (int ci = 0; ci < CA; ci++) {
        const float* ch = sI + ci * CSZ + h * PITCH + w0;
        #pragma unroll
        for (int kh = 0; kh < 3; kh++) {
            float v[NPIX + 2];
            #pragma unroll
            for (int j = 0; j < NPIX + 2; j++) v[j] = ch[kh * PITCH + j];
            const float* wr = sW + (ci * 9 + kh * 3) * COUT + cog * COUT_T;
            #pragma unroll
            for (int co = 0; co < COUT_T; co++) {
                float wa = wr[co], wb = wr[COUT + co], wc = wr[2 * COUT + co];
                #pragma unroll
                for (int j = 0; j < NPIX; j++)
                    acc[co][j] = fmaf(wa, v[j], fmaf(wb, v[j + 1], fmaf(wc, v[j + 2], acc[co][j])));
            }
        }
    }

    const int btn = bt0 + n;
    #pragma unroll
    for (int co = 0; co < COUT_T; co++) {
        float* op = out + (size_t)((btn * COUT + cog * COUT_T + co) * HS + h) * HS + w0;
        #pragma unroll
        for (int j = 0; j < NPIX; j += 4)
            *reinterpret_cast<float4*>(op + j) =
                make_float4(fmaxf(acc[co][j], 0.f), fmaxf(acc[co][j + 1], 0.f),
                            fmaxf(acc[co][j + 2], 0.f), fmaxf(acc[co][j + 3], 0.f));
    }
}

// -------------------- decoder conv3x3 over [up2x(A), B] + ReLU ---------------
// Coarse A kept at HA=HS/2 (parity-folded 2x2 stencil), halo-padded; fine B halo-padded.
template<int CA, int CB, int COUT, int COUT_T, int HS, int NBT, int NPIX,
         int PA, int PB, int NTH, int MINB>
__global__ void __launch_bounds__(NTH, MINB)
conv_up_k(const float* __restrict__ inA, const float* __restrict__ inB,
          const float* __restrict__ wgt, const float* __restrict__ bias,
          float* __restrict__ out)
{
    constexpr int CIN   = CA + CB;
    constexpr int HA    = HS / 2;
    constexpr int CROWS = HA + 2;
    constexpr int FROWS = HS + 2;
    constexpr int CASZ  = CROWS * PA;
    constexpr int CBSZ  = FROWS * PB;
    constexpr int ASZ   = CA * CASZ;
    constexpr int TSZ   = ASZ + CB * CBSZ;
    constexpr int GP    = COUT / COUT_T;
    constexpr int PXT   = HS * HS / NPIX;
    constexpr int WSZ   = COUT * CIN * 9;
    constexpr int NC    = NPIX / 2 + 2;

    extern __shared__ float sm[];
    float* sW  = sm;
    float* sBi = sW + WSZ;
    float* sIn = sBi + COUT;

    const int tid = threadIdx.x, NT = blockDim.x;
    const int bt0 = blockIdx.x * NBT;

    for (int i = tid; i < WSZ; i += NT) {
        int co = i % COUT;
        int rest = i / COUT;
        int ci = rest / 9, kk = rest % 9;
        sW[i] = wgt[(co * CIN + ci) * 9 + kk];
    }
    for (int i = tid; i < COUT; i += NT) sBi[i] = bias[i];

    for (int i = tid; i < NBT * ASZ; i += NT) {
        int nn = i / ASZ, r2 = i % ASZ;
        int c = r2 / CASZ, cell = r2 % CASZ;
        int row = cell / PA, col = cell % PA;
        int hh = row - 1, ww = col - 1;
        float v = 0.f;
        if (hh >= 0 && hh < HA && ww >= 0 && ww < HA)
            v = inA[(size_t)((bt0 + nn) * CA + c) * (HA * HA) + hh * HA + ww];
        sIn[nn * TSZ + c * CASZ + cell] = v;
    }
    for (int i = tid; i < NBT * CB * CBSZ; i += NT) {
        int nn = i / (CB * CBSZ), r2 = i % (CB * CBSZ);
        int c = r2 / CBSZ, cell = r2 % CBSZ;
        int row = cell / PB, col = cell % PB;
        int hh = row - 1, ww = col - 1;
        float v = 0.f;
        if (hh >= 0 && hh < HS && ww >= 0 && ww < HS)
            v = inB[(size_t)((bt0 + nn) * CB + c) * (HS * HS) + hh * HS + ww];
        sIn[nn * TSZ + ASZ + c * CBSZ + cell] = v;
    }
    __syncthreads();

    const int n   = tid / (GP * PXT);
    const int r   = tid % (GP * PXT);
    const int cog = r / PXT;
    const int p   = r % PXT;
    const int h   = p / (HS / NPIX);
    const int w0  = (p % (HS / NPIX)) * NPIX;
    const float* sI = sIn + n * TSZ;

    float acc[COUT_T][NPIX];
    #pragma unroll
    for (int co = 0; co < COUT_T; co++) {
        float b = sBi[cog * COUT_T + co];
        #pragma unroll
        for (int j = 0; j < NPIX; j++) acc[co][j] = b;
    }

    // ---- A part: coarse 2x2 stencil, halo-padded (no predicates) ----
    const int  a     = h >> 1;
    const bool hodd  = (h & 1) != 0;
    const int  prA   = hodd ? (a + 1) : a;
    const int  cbase = (w0 >> 1);

    #pragma unroll 1
    for (int ci = 0; ci < CA; ci++) {
        const float* ch = sI + ci * CASZ;
        float cAr[NC], cBr[NC];
        #pragma unroll
        for (int k = 0; k < NC; k++) {
            cAr[k] = ch[prA * PA + cbase + k];
            cBr[k] = ch[(prA + 1) * PA + cbase + k];
        }
        const float* wr = sW + ci * 9 * COUT + cog * COUT_T;
        #pragma unroll
        for (int co = 0; co < COUT_T; co++) {
            float w00 = wr[0 * COUT + co], w01 = wr[1 * COUT + co], w02 = wr[2 * COUT + co];
            float w10 = wr[3 * COUT + co], w11 = wr[4 * COUT + co], w12 = wr[5 * COUT + co];
            float w20 = wr[6 * COUT + co], w21 = wr[7 * COUT + co], w22 = wr[8 * COUT + co];
            float rA0 = hodd ? (w00 + w10) : w00;
            float rA1 = hodd ? (w01 + w11) : w01;
            float rA2 = hodd ? (w02 + w12) : w02;
            float rB0 = hodd ? w20 : (w10 + w20);
            float rB1 = hodd ? w21 : (w11 + w21);
            float rB2 = hodd ? w22 : (w12 + w22);
            float sA0 = rA0, sA01 = rA0 + rA1, sA12 = rA1 + rA2, sA2 = rA2;
            float sB0 = rB0, sB01 = rB0 + rB1, sB12 = rB1 + rB2, sB2 = rB2;
            #pragma unroll
            for (int j = 0; j < NPIX; j++) {
                int lb = (j >> 1) + 1;
                if ((j & 1) == 0) {
                    acc[co][j] = fmaf(cAr[lb - 1], sA0,  acc[co][j]);
                    acc[co][j] = fmaf(cAr[lb],     sA12, acc[co][j]);
                    acc[co][j] = fmaf(cBr[lb - 1], sB0,  acc[co][j]);
                    acc[co][j] = fmaf(cBr[lb],     sB12, acc[co][j]);
                } else {
                    acc[co][j] = fmaf(cAr[lb],     sA01, acc[co][j]);
                    acc[co][j] = fmaf(cAr[lb + 1], sA2,  acc[co][j]);
                    acc[co][j] = fmaf(cBr[lb],     sB01, acc[co][j]);
                    acc[co][j] = fmaf(cBr[lb + 1], sB2,  acc[co][j]);
                }
            }
        }
    }

    // ---- B part: fine 3x3, halo-padded (no predicates) ----
    #pragma unroll 1
    for (int ci = 0; ci < CB; ci++) {
        const float* ch = sI + ASZ + ci * CBSZ + h * PB + w0;
        #pragma unroll
        for (int kh = 0; kh < 3; kh++) {
            float v[NPIX + 2];
            #pragma unroll
            for (int j = 0; j < NPIX + 2; j++) v[j] = ch[kh * PB + j];
            const float* wr = sW + ((CA + ci) * 9 + kh * 3) * COUT + cog * COUT_T;
            #pragma unroll
            for (int co = 0; co < COUT_T; co++) {
                float wa = wr[co], wb = wr[COUT + co], wc = wr[2 * COUT + co];
                #pragma unroll
                for (int j = 0; j < NPIX; j++)
                    acc[co][j] = fmaf(wa, v[j], fmaf(wb, v[j + 1], fmaf(wc, v[j + 2], acc[co][j])));
            }
        }
    }

    const int btn = bt0 + n;
    #pragma unroll
    for (int co = 0; co < COUT_T; co++) {
        float* op = out + (size_t)((btn * COUT + cog * COUT_T + co) * HS + h) * HS + w0;
        #pragma unroll
        for (int j = 0; j < NPIX; j += 4)
            *reinterpret_cast<float4*>(op + j) =
                make_float4(fmaxf(acc[co][j], 0.f), fmaxf(acc[co][j + 1], 0.f),
                            fmaxf(acc[co][j + 2], 0.f), fmaxf(acc[co][j + 3], 0.f));
    }
}

// -------------------- 1x1 conv -> softmax(3ch incl. ones) -> masked feat ----
__global__ void mask_feat_kernel(const float* __restrict__ d1, const float* __restrict__ xt,
                                 const float* __restrict__ ow, const float* __restrict__ ob,
                                 float* __restrict__ feat)
{
    int idx = blockIdx.x * blockDim.x + threadIdx.x;
    if (idx >= BT * 1024) return;
    int bt = idx >> 10, hw = idx & 1023;
    const float* dp = d1 + (size_t)bt * 8 * 1024 + hw;
    float l0 = ob[0], l1 = ob[1];
    #pragma unroll
    for (int c = 0; c < 8; c++) {
        float v = dp[(size_t)c << 10];
        l0 = fmaf(v, ow[c], l0);
        l1 = fmaf(v, ow[8 + c], l1);
    }
    float mx = fmaxf(fmaxf(l0, l1), 1.0f);
    float e0 = expf(l0 - mx), e1 = expf(l1 - mx), e2 = expf(1.0f - mx);
    float inv = 1.0f / (e0 + e1 + e2);
    float m0 = e0 * inv, m1 = e1 * inv;

    const float* xp = xt + (size_t)bt * 3 * 1024 + hw;
    float* fp = feat + (size_t)bt * FEAT + hw;
    #pragma unroll
    for (int c = 0; c < 3; c++) {
        float xv = xp[(size_t)c << 10];
        fp[(size_t)c << 10]       = m0 * xv;
        fp[(size_t)(3 + c) << 10] = m1 * xv;
    }
}

// -------------------- GEMM1: split-K, BM256/BN64/BK16, TM16/TN4 --------------
__global__ void __launch_bounds__(256)
sgemm1_k(const float* __restrict__ A, const float* __restrict__ Bm,
         float* __restrict__ Cpart)
{
    constexpr int M = BT, N = HID, K = FEAT;
    constexpr int BM = 256, BN = 64, BK = 16;
    constexpr int KS = K / SPLITS;  // 768
    __shared__ float sA[BK][BM + 4];
    __shared__ float sB[BK][BN + 4];

    const int tid = threadIdx.x;
    const int tx = tid % 16;
    const int ty = tid / 16;
    const int bm = blockIdx.y * BM;
    const int bn = blockIdx.x * BN;
    const int kbase = blockIdx.z * KS;

    const int c4 = tid % 4;
    const int r0 = tid / 4;

    float acc[16][4];
    #pragma unroll
    for (int i = 0; i < 16; i++)
        #pragma unroll
        for (int j = 0; j < 4; j++) acc[i][j] = 0.f;

    for (int k0 = kbase; k0 < kbase + KS; k0 += BK) {
        #pragma unroll
        for (int q = 0; q < 4; q++) {
            int rr = r0 + 64 * q;
            float4 av = *reinterpret_cast<const float4*>(&A[(size_t)(bm + rr) * K + k0 + c4 * 4]);
            sA[c4 * 4 + 0][rr] = av.x;
            sA[c4 * 4 + 1][rr] = av.y;
            sA[c4 * 4 + 2][rr] = av.z;
            sA[c4 * 4 + 3][rr] = av.w;
        }
        {
            int kk = tid / 16;
            int cc = (tid % 16) * 4;
            int gcol = bn + cc;
            float4 bv;
            if (gcol + 3 < N) {
                bv = *reinterpret_cast<const float4*>(&Bm[(size_t)(k0 + kk) * N + gcol]);
            } else {
                bv.x = (gcol + 0 < N) ? Bm[(size_t)(k0 + kk) * N + gcol + 0] : 0.f;
                bv.y = (gcol + 1 < N) ? Bm[(size_t)(k0 + kk) * N + gcol + 1] : 0.f;
                bv.z = (gcol + 2 < N) ? Bm[(size_t)(k0 + kk) * N + gcol + 2] : 0.f;
                bv.w = (gcol + 3 < N) ? Bm[(size_t)(k0 + kk) * N + gcol + 3] : 0.f;
            }
            *reinterpret_cast<float4*>(&sB[kk][cc]) = bv;
        }
        __syncthreads();

        #pragma unroll
        for (int kk = 0; kk < BK; kk++) {
            float4 b = *reinterpret_cast<const float4*>(&sB[kk][tx * 4]);
            #pragma unroll
            for (int q = 0; q < 4; q++) {
                float4 a = *reinterpret_cast<const float4*>(&sA[kk][ty * 16 + q * 4]);
                acc[q * 4 + 0][0] = fmaf(a.x, b.x, acc[q * 4 + 0][0]);
                acc[q * 4 + 0][1] = fmaf(a.x, b.y, acc[q * 4 + 0][1]);
                acc[q * 4 + 0][2] = fmaf(a.x, b.z, acc[q * 4 + 0][2]);
                acc[q * 4 + 0][3] = fmaf(a.x, b.w, acc[q * 4 + 0][3]);
                acc[q * 4 + 1][0] = fmaf(a.y, b.x, acc[q * 4 + 1][0]);
                acc[q * 4 + 1][1] = fmaf(a.y, b.y, acc[q * 4 + 1][1]);
                acc[q * 4 + 1][2] = fmaf(a.y, b.z, acc[q * 4 + 1][2]);
                acc[q * 4 + 1][3] = fmaf(a.y, b.w, acc[q * 4 + 1][3]);
                acc[q * 4 + 2][0] = fmaf(a.z, b.x, acc[q * 4 + 2][0]);
                acc[q * 4 + 2][1] = fmaf(a.z, b.y, acc[q * 4 + 2][1]);
                acc[q * 4 + 2][2] = fmaf(a.z, b.z, acc[q * 4 + 2][2]);
                acc[q * 4 + 2][3] = fmaf(a.z, b.w, acc[q * 4 + 2][3]);
                acc[q * 4 + 3][0] = fmaf(a.w, b.x, acc[q * 4 + 3][0]);
                acc[q * 4 + 3][1] = fmaf(a.w, b.y, acc[q * 4 + 3][1]);
                acc[q * 4 + 3][2] = fmaf(a.w, b.z, acc[q * 4 + 3][2]);
                acc[q * 4 + 3][3] = fmaf(a.w, b.w, acc[q * 4 + 3][3]);
            }
        }
        __syncthreads();
    }

    float* Cp = Cpart + (size_t)blockIdx.z * M * N;
    #pragma unroll
    for (int i = 0; i < 16; i++) {
        int m = bm + ty * 16 + i;
        #pragma unroll
        for (int j = 0; j < 4; j++) {
            int n = bn + tx * 4 + j;
            if (n < N) Cp[(size_t)m * N + n] = acc[i][j];
        }
    }
}

__global__ void reduce8_relu_kernel(const float* __restrict__ part,
                                    const float* __restrict__ bias,
                                    float* __restrict__ out)
{
    int idx = blockIdx.x * blockDim.x + threadIdx.x;
    if (idx >= BT * HID) return;
    int n = idx % HID;
    float v = bias[n];
    #pragma unroll
    for (int s = 0; s < SPLITS; s++) v += part[(size_t)s * BT * HID + idx];
    out[idx] = fmaxf(v, 0.f);
}

// -------------------- tiled SGEMM (GEMM2, bias+relu) --------------------------
template<int BM, int BN, int BK, int TM, int TN, bool RELU>
__global__ void sgemm_k(int M, int N, int K,
                        const float* __restrict__ A, const float* __restrict__ Bm,
                        const float* __restrict__ bias, float* __restrict__ C)
{
    __shared__ float sA[BK][BM + 1];
    __shared__ float sB[BK][BN];
    const int tid = threadIdx.x;
    const int tx = tid % (BN / TN);
    const int ty = tid / (BN / TN);
    const int bm = blockIdx.y * BM;
    const int bn = blockIdx.x * BN;

    float acc[TM][TN];
    #pragma unroll
    for (int i = 0; i < TM; i++)
        #pragma unroll
        for (int j = 0; j < TN; j++) acc[i][j] = 0.f;

    for (int k0 = 0; k0 < K; k0 += BK) {
        for (int i = tid; i < BM * BK; i += 256) {
            int m = i / BK, kk = i % BK;
            sA[kk][m] = (bm + m < M && k0 + kk < K) ? A[(size_t)(bm + m) * K + k0 + kk] : 0.f;
        }
        for (int i = tid; i < BK * BN; i += 256) {
            int kk = i / BN, n = i % BN;
            sB[kk][n] = (k0 + kk < K && bn + n < N) ? Bm[(size_t)(k0 + kk) * N + bn + n] : 0.f;
        }
        __syncthreads();
        #pragma unroll
        for (int kk = 0; kk < BK; kk++) {
            float a[TM], b[TN];
            #pragma unroll
            for (int i = 0; i < TM; i++) a[i] = sA[kk][ty * TM + i];
            #pragma unroll
            for (int j = 0; j < TN; j++) b[j] = sB[kk][tx * TN + j];
            #pragma unroll
            for (int i = 0; i < TM; i++)
                #pragma unroll
                for (int j = 0; j < TN; j++) acc[i][j] = fmaf(a[i], b[j], acc[i][j]);
        }
        __syncthreads();
    }

    #pragma unroll
    for (int i = 0; i < TM; i++) {
        int m = bm + ty * TM + i;
        if (m >= M) continue;
        #pragma unroll
        for (int j = 0; j < TN; j++) {
            int n = bn + tx * TN + j;
            if (n >= N) continue;
            float v = acc[i][j] + bias[n];
            if (RELU) v = fmaxf(v, 0.f);
            C[(size_t)m * N + n] = v;
        }
    }
}

// -------------------- final 200->4 + tanh scale ------------------------------
__global__ void loc3_kernel(const float* __restrict__ h2, const float* __restrict__ w3,
                            const float* __restrict__ b3, float* __restrict__ out)
{
    int idx = blockIdx.x * blockDim.x + threadIdx.x;
    if (idx >= BT * 4) return;
    int m = idx >> 2, j = idx & 3;
    float acc = b3[j];
    const float* hp = h2 + (size_t)m * HID;
    #pragma unroll 8
    for (int k = 0; k < HID; k++) acc = fmaf(hp[k], w3[k * 4 + j], acc);
    out[idx] = tanhf(acc) * 16.f + 16.f;
}

// -------------------- launch --------------------------------------------------
extern "C" void kernel_launch(void* const* d_in, const int* in_sizes, int n_in,
                              void* d_out, int out_size)
{
    const float* x   = (const float*)d_in[0];
    const float* ew1 = (const float*)d_in[1];
    const float* eb1 = (const float*)d_in[2];
    const float* ew2 = (const float*)d_in[3];
    const float* eb2 = (const float*)d_in[4];
    const float* ew3 = (const float*)d_in[5];
    const float* eb3 = (const float*)d_in[6];
    const float* dw2 = (const float*)d_in[7];
    const float* db2 = (const float*)d_in[8];
    const float* dw1 = (const float*)d_in[9];
    const float* db1 = (const float*)d_in[10];
    const float* ow  = (const float*)d_in[11];
    const float* ob  = (const float*)d_in[12];
    const float* lw1 = (const float*)d_in[13];
    const float* lb1 = (const float*)d_in[14];
    const float* lw2 = (const float*)d_in[15];
    const float* lb2 = (const float*)d_in[16];
    const float* lw3 = (const float*)d_in[17];
    const float* lb3 = (const float*)d_in[18];
    float* out = (float*)d_out;

    float *xt, *e1, *e2, *e3, *d2v, *d1v, *feat, *h1, *h2, *part;
    cudaGetSymbolAddress((void**)&xt,   g_xt);
    cudaGetSymbolAddress((void**)&e1,   g_e1);
    cudaGetSymbolAddress((void**)&e2,   g_e2);
    cudaGetSymbolAddress((void**)&e3,   g_e3);
    cudaGetSymbolAddress((void**)&d2v,  g_d2);
    cudaGetSymbolAddress((void**)&d1v,  g_d1);
    cudaGetSymbolAddress((void**)&feat, g_feat);
    cudaGetSymbolAddress((void**)&h1,   g_h1);
    cudaGetSymbolAddress((void**)&h2,   g_h2);
    cudaGetSymbolAddress((void**)&part, g_part);

    // smem bytes (halo-padded layouts)
    constexpr int SM_E1 = (3 * 8 * 9   + 8  + 2 * 3 * 34 * 35) * 4;                     // 29456
    constexpr int SM_E2 = (8 * 16 * 9  + 16 + 4 * 8 * 18 * 23) * 4;                     // 57664
    constexpr int SM_E3 = (16 * 32 * 9 + 32 + 8 * 16 * 10 * 11) * 4;                    // 74880
    constexpr int SM_D2 = (48 * 16 * 9 + 16 + 2 * (32 * 10 * 11 + 16 * 18 * 23)) * 4;   // 108864
    constexpr int SM_D1 = (24 * 8 * 9  + 8  + 1 * (16 * 18 * 21 + 8 * 34 * 35)) * 4;    // 69216

    cudaFuncSetAttribute((const void*)conv_std_k<8, 16, 8, 16, 4, 8, true, 23>,
                         cudaFuncAttributeMaxDynamicSharedMemorySize, SM_E2);
    cudaFuncSetAttribute((const void*)conv_std_k<16, 32, 8, 8, 8, 8, true, 11>,
                         cudaFuncAttributeMaxDynamicSharedMemorySize, SM_E3);
    cudaFuncSetAttribute((const void*)conv_up_k<32, 16, 16, 4, 16, 2, 8, 11, 23, 256, 2>,
                         cudaFuncAttributeMaxDynamicSharedMemorySize, SM_D2);
    cudaFuncSetAttribute((const void*)conv_up_k<16, 8, 8, 8, 32, 1, 8, 21, 35, 128, 3>,
                         cudaFuncAttributeMaxDynamicSharedMemorySize, SM_D1);

    // 1) permute
    permute_kernel<<<32 * 3 * 32, 256>>>(x, xt);
    // 2) e1 = relu(conv 3->8 @32)  — 2 imgs/block, 256 thr (COUT_T=8)
    conv_std_k<3, 8, 8, 32, 2, 8, false, 35><<<BT / 2, 256, SM_E1>>>(xt, ew1, eb1, e1);
    // 3) e2 = relu(conv pool(e1) 8->16 @16) — 4 imgs/block, 256 thr
    conv_std_k<8, 16, 8, 16, 4, 8, true, 23><<<BT / 4, 256, SM_E2>>>(e1, ew2, eb2, e2);
    // 4) e3 = relu(conv pool(e2) 16->32 @8) — 8 imgs/block, 256 thr
    conv_std_k<16, 32, 8, 8, 8, 8, true, 11><<<BT / 8, 256, SM_E3>>>(e2, ew3, eb3, e3);
    // 5) d2 = relu(conv [up(e3), e2] 48->16 @16) — COUT_T=4, 2 imgs/block, 256 thr
    conv_up_k<32, 16, 16, 4, 16, 2, 8, 11, 23, 256, 2><<<BT / 2, 256, SM_D2>>>(e3, e2, dw2, db2, d2v);
    // 6) d1 = relu(conv [up(d2), e1] 24->8 @32) — COUT_T=8, 1 img/block, 128 thr
    conv_up_k<16, 8, 8, 8, 32, 1, 8, 21, 35, 128, 3><<<BT, 128, SM_D1>>>(d2v, e1, dw1, db1, d1v);
    // 7) masks + masked features
    mask_feat_kernel<<<(BT * 1024) / 256, 256>>>(d1v, xt, ow, ob, feat);
    // 8) h1 = relu(feat @ lw1 + lb1) via split-K x8
    sgemm1_k<<<dim3(4, BT / 256, SPLITS), 256>>>(feat, lw1, part);
    reduce8_relu_kernel<<<(BT * HID + 255) / 256, 256>>>(part, lb1, h1);
    // 9) h2 = relu(h1 @ lw2 + lb2)
    sgemm_k<64, 64, 16, 4, 4, true><<<dim3(4, BT / 64), 256>>>(BT, HID, HID, h1, lw2, lb2, h2);
    // 10) out = tanh(h2 @ lw3 + lb3)*16+16
    loc3_kernel<<<(BT * 4 + 255) / 256, 256>>>(h2, lw3, lb3, out);
}

// round 7
// speedup vs baseline: 1.3937x; 1.3937x over previous
#include <cuda_runtime.h>
#include <cuda_bf16.h>
#include <math.h>

#define BB 32
#define TT 64
#define BT 2048
#define HID 200
#define FEAT 6144
#define SPLITS 8

// -------------------- scratch (device globals; no allocs) --------------------
__device__ float g_xt  [BT * 3  * 1024];
__device__ float g_e1  [BT * 8  * 1024];
__device__ float g_e2  [BT * 16 * 256];
__device__ float g_e3  [BT * 32 * 64];
__device__ float g_d2  [BT * 16 * 256];
__device__ float g_d1  [BT * 8  * 1024];
__device__ float g_feat[BT * FEAT];
__device__ float g_h1  [BT * HID];
__device__ float g_h2  [BT * HID];
__device__ float g_part[SPLITS * BT * HID];

// -------------------- permute [B,C,H,W,T] -> [B*T,C,H,W] --------------------
__global__ void permute_kernel(const float* __restrict__ x, float* __restrict__ xt) {
    int bidx = blockIdx.x;
    int h = bidx & 31;
    int c = (bidx >> 5) % 3;
    int b = bidx / 96;
    __shared__ float s[32][65];
    const float* src = x + (size_t)(((b * 3 + c) * 32 + h) * 32) * 64;
    for (int i = threadIdx.x; i < 2048; i += blockDim.x) {
        int w = i >> 6, t = i & 63;
        s[w][t] = src[i];
    }
    __syncthreads();
    for (int i = threadIdx.x; i < 2048; i += blockDim.x) {
        int t = i >> 5, w = i & 31;
        xt[((size_t)((b * 64 + t) * 3 + c) << 10) + (h << 5) + w] = s[w][t];
    }
}

// -------------------- standard conv3x3 (+optional 2x2 maxpool of input, +ReLU)
// SMEM: input rows padded to HS+1 (bank-conflict-free h-strided loads);
//       weights transposed to [ci][kh][kw][co] (conflict-free/broadcast).
template<int CA, int COUT, int COUT_T, int HS, int NBT, int NPIX, bool POOL>
__global__ void __launch_bounds__(256, 2)
conv_std_k(const float* __restrict__ inA, const float* __restrict__ wgt,
           const float* __restrict__ bias, float* __restrict__ out)
{
    constexpr int GP   = COUT / COUT_T;
    constexpr int PXT  = HS * HS / NPIX;
    constexpr int HP   = HS + 1;                 // padded row pitch
    constexpr int CSZ  = HS * HP;                // padded channel size
    constexpr int ASZP = CA * CSZ;
    constexpr int WSZ  = COUT * CA * 9;
    extern __shared__ float sm[];
    float* sW  = sm;                  // transposed weights [CA*9][COUT]
    float* sBi = sW + WSZ;
    float* sIn = sBi + COUT;

    const int tid = threadIdx.x, NT = blockDim.x;
    const int bt0 = blockIdx.x * NBT;

    // weights transposed: sW[(ci*9 + kh*3 + kw)*COUT + co]
    for (int i = tid; i < WSZ; i += NT) {
        int co = i % COUT;
        int rest = i / COUT;          // ci*9 + kh*3 + kw
        int ci = rest / 9, kk = rest % 9;
        sW[i] = wgt[(co * CA + ci) * 9 + kk];
    }
    for (int i = tid; i < COUT; i += NT) sBi[i] = bias[i];

    for (int i = tid; i < NBT * CA * HS * HS; i += NT) {
        int nn = i / (CA * HS * HS), rr = i % (CA * HS * HS);
        int c = rr / (HS * HS), pp = rr % (HS * HS);
        int hh = pp / HS, ww = pp % HS;
        float v;
        if (POOL) {
            const float* s = inA + (size_t)((bt0 + nn) * CA + c) * (4 * HS * HS)
                                 + (2 * hh) * (2 * HS) + 2 * ww;
            v = fmaxf(fmaxf(s[0], s[1]), fmaxf(s[2 * HS], s[2 * HS + 1]));
        } else {
            v = inA[(size_t)(bt0 + nn) * (CA * HS * HS) + rr];
        }
        sIn[nn * ASZP + c * CSZ + hh * HP + ww] = v;
    }
    __syncthreads();

    const int n   = tid / (GP * PXT);
    const int r   = tid % (GP * PXT);
    const int cog = r / PXT;
    const int p   = r % PXT;
    const int h   = p / (HS / NPIX);
    const int w0  = (p % (HS / NPIX)) * NPIX;
    const float* sI = sIn + n * ASZP;

    float acc[COUT_T][NPIX];
    #pragma unroll
    for (int co = 0; co < COUT_T; co++) {
        float b = sBi[cog * COUT_T + co];
        #pragma unroll
        for (int j = 0; j < NPIX; j++) acc[co][j] = b;
    }

    #pragma unroll 1
    for (int ci = 0; ci < CA; ci++) {
        const float* ch = sI + ci * CSZ;
        #pragma unroll
        for (int kh = 0; kh < 3; kh++) {
            int ih = h + kh - 1;
            bool rowok = (ih >= 0) && (ih < HS);
            float v[NPIX + 2];
            #pragma unroll
            for (int j = 0; j < NPIX + 2; j++) {
                int iw = w0 + j - 1;
                v[j] = (rowok && iw >= 0 && iw < HS) ? ch[ih * HP + iw] : 0.f;
            }
            const float* wr = sW + (ci * 9 + kh * 3) * COUT + cog * COUT_T;
            #pragma unroll
            for (int co = 0; co < COUT_T; co++) {
                float wa = wr[co], wb = wr[COUT + co], wc = wr[2 * COUT + co];
                #pragma unroll
                for (int j = 0; j < NPIX; j++)
                    acc[co][j] = fmaf(wa, v[j], fmaf(wb, v[j + 1], fmaf(wc, v[j + 2], acc[co][j])));
            }
        }
    }

    const int btn = bt0 + n;
    #pragma unroll
    for (int co = 0; co < COUT_T; co++) {
        float* op = out + (size_t)((btn * COUT + cog * COUT_T + co) * HS + h) * HS + w0;
        #pragma unroll
        for (int j = 0; j < NPIX; j += 4)
            *reinterpret_cast<float4*>(op + j) =
                make_float4(fmaxf(acc[co][j], 0.f), fmaxf(acc[co][j + 1], 0.f),
                            fmaxf(acc[co][j + 2], 0.f), fmaxf(acc[co][j + 3], 0.f));
    }
}

// -------------------- decoder conv3x3 over [up2x(A), B] + ReLU ---------------
// A kept at coarse HA=HS/2 (parity-folded 2x2 stencil). Padded rows + transposed W.
template<int CA, int CB, int COUT, int COUT_T, int HS, int NBT, int NPIX>
__global__ void __launch_bounds__(256, 2)
conv_up_k(const float* __restrict__ inA, const float* __restrict__ inB,
          const float* __restrict__ wgt, const float* __restrict__ bias,
          float* __restrict__ out)
{
    constexpr int CIN  = CA + CB;
    constexpr int HA   = HS / 2;
    constexpr int HAP  = HA + 1;
    constexpr int HP   = HS + 1;
    constexpr int CASZ = HA * HAP;        // padded coarse channel
    constexpr int CBSZ = HS * HP;         // padded fine channel
    constexpr int ASZP = CA * CASZ;
    constexpr int TSZ  = ASZP + CB * CBSZ;
    constexpr int GP   = COUT / COUT_T;
    constexpr int PXT  = HS * HS / NPIX;
    constexpr int WSZ  = COUT * CIN * 9;
    constexpr int NC   = NPIX / 2 + 2;

    extern __shared__ float sm[];
    float* sW  = sm;                  // transposed [CIN*9][COUT]
    float* sBi = sW + WSZ;
    float* sIn = sBi + COUT;

    const int tid = threadIdx.x, NT = blockDim.x;
    const int bt0 = blockIdx.x * NBT;

    for (int i = tid; i < WSZ; i += NT) {
        int co = i % COUT;
        int rest = i / COUT;
        int ci = rest / 9, kk = rest % 9;
        sW[i] = wgt[(co * CIN + ci) * 9 + kk];
    }
    for (int i = tid; i < COUT; i += NT) sBi[i] = bias[i];
    for (int i = tid; i < NBT * CA * HA * HA; i += NT) {
        int nn = i / (CA * HA * HA), rr = i % (CA * HA * HA);
        int c = rr / (HA * HA), pp = rr % (HA * HA);
        sIn[nn * TSZ + c * CASZ + (pp / HA) * HAP + (pp % HA)] =
            inA[(size_t)(bt0 + nn) * (CA * HA * HA) + rr];
    }
    for (int i = tid; i < NBT * CB * HS * HS; i += NT) {
        int nn = i / (CB * HS * HS), rr = i % (CB * HS * HS);
        int c = rr / (HS * HS), pp = rr % (HS * HS);
        sIn[nn * TSZ + ASZP + c * CBSZ + (pp / HS) * HP + (pp % HS)] =
            inB[(size_t)(bt0 + nn) * (CB * HS * HS) + rr];
    }
    __syncthreads();

    const int n   = tid / (GP * PXT);
    const int r   = tid % (GP * PXT);
    const int cog = r / PXT;
    const int p   = r % PXT;
    const int h   = p / (HS / NPIX);
    const int w0  = (p % (HS / NPIX)) * NPIX;
    const float* sI = sIn + n * TSZ;

    float acc[COUT_T][NPIX];
    #pragma unroll
    for (int co = 0; co < COUT_T; co++) {
        float b = sBi[cog * COUT_T + co];
        #pragma unroll
        for (int j = 0; j < NPIX; j++) acc[co][j] = b;
    }

    // ---- A part: coarse 2x2 stencil with parity-folded weights ----
    const int  a    = h >> 1;
    const bool hodd = (h & 1) != 0;
    const int  rowA = hodd ? a : a - 1;
    const int  rowB = hodd ? a + 1 : a;
    const int  cs0  = (w0 >> 1) - 1;

    #pragma unroll 1
    for (int ci = 0; ci < CA; ci++) {
        const float* ch = sI + ci * CASZ;
        float cAr[NC], cBr[NC];
        #pragma unroll
        for (int k = 0; k < NC; k++) {
            int cc = cs0 + k;
            bool cok = (cc >= 0) && (cc < HA);
            cAr[k] = (cok && rowA >= 0) ? ch[rowA * HAP + cc] : 0.f;
            cBr[k] = (cok && rowB < HA) ? ch[rowB * HAP + cc] : 0.f;
        }
        const float* wr = sW + ci * 9 * COUT + cog * COUT_T;
        #pragma unroll
        for (int co = 0; co < COUT_T; co++) {
            float w00 = wr[0 * COUT + co], w01 = wr[1 * COUT + co], w02 = wr[2 * COUT + co];
            float w10 = wr[3 * COUT + co], w11 = wr[4 * COUT + co], w12 = wr[5 * COUT + co];
            float w20 = wr[6 * COUT + co], w21 = wr[7 * COUT + co], w22 = wr[8 * COUT + co];
            float rA0 = hodd ? (w00 + w10) : w00;
            float rA1 = hodd ? (w01 + w11) : w01;
            float rA2 = hodd ? (w02 + w12) : w02;
            float rB0 = hodd ? w20 : (w10 + w20);
            float rB1 = hodd ? w21 : (w11 + w21);
            float rB2 = hodd ? w22 : (w12 + w22);
            float sA0 = rA0, sA01 = rA0 + rA1, sA12 = rA1 + rA2, sA2 = rA2;
            float sB0 = rB0, sB01 = rB0 + rB1, sB12 = rB1 + rB2, sB2 = rB2;
            #pragma unroll
            for (int j = 0; j < NPIX; j++) {
                int lb = (j >> 1) + 1;
                if ((j & 1) == 0) {
                    acc[co][j] = fmaf(cAr[lb - 1], sA0,  acc[co][j]);
                    acc[co][j] = fmaf(cAr[lb],     sA12, acc[co][j]);
                    acc[co][j] = fmaf(cBr[lb - 1], sB0,  acc[co][j]);
                    acc[co][j] = fmaf(cBr[lb],     sB12, acc[co][j]);
                } else {
                    acc[co][j] = fmaf(cAr[lb],     sA01, acc[co][j]);
                    acc[co][j] = fmaf(cAr[lb + 1], sA2,  acc[co][j]);
                    acc[co][j] = fmaf(cBr[lb],     sB01, acc[co][j]);
                    acc[co][j] = fmaf(cBr[lb + 1], sB2,  acc[co][j]);
                }
            }
        }
    }

    // ---- B part: standard fine 3x3 ----
    #pragma unroll 1
    for (int ci = 0; ci < CB; ci++) {
        const float* ch = sI + ASZP + ci * CBSZ;
        #pragma unroll
        for (int kh = 0; kh < 3; kh++) {
            int ih = h + kh - 1;
            bool rowok = (ih >= 0) && (ih < HS);
            float v[NPIX + 2];
            #pragma unroll
            for (int j = 0; j < NPIX + 2; j++) {
                int iw = w0 + j - 1;
                v[j] = (rowok && iw >= 0 && iw < HS) ? ch[ih * HP + iw] : 0.f;
            }
            const float* wr = sW + ((CA + ci) * 9 + kh * 3) * COUT + cog * COUT_T;
            #pragma unroll
            for (int co = 0; co < COUT_T; co++) {
                float wa = wr[co], wb = wr[COUT + co], wc = wr[2 * COUT + co];
                #pragma unroll
                for (int j = 0; j < NPIX; j++)
                    acc[co][j] = fmaf(wa, v[j], fmaf(wb, v[j + 1], fmaf(wc, v[j + 2], acc[co][j])));
            }
        }
    }

    const int btn = bt0 + n;
    #pragma unroll
    for (int co = 0; co < COUT_T; co++) {
        float* op = out + (size_t)((btn * COUT + cog * COUT_T + co) * HS + h) * HS + w0;
        #pragma unroll
        for (int j = 0; j < NPIX; j += 4)
            *reinterpret_cast<float4*>(op + j) =
                make_float4(fmaxf(acc[co][j], 0.f), fmaxf(acc[co][j + 1], 0.f),
                            fmaxf(acc[co][j + 2], 0.f), fmaxf(acc[co][j + 3], 0.f));
    }
}

// -------------------- 1x1 conv -> softmax(3ch incl. ones) -> masked feat ----
__global__ void mask_feat_kernel(const float* __restrict__ d1, const float* __restrict__ xt,
                                 const float* __restrict__ ow, const float* __restrict__ ob,
                                 float* __restrict__ feat)
{
    int idx = blockIdx.x * blockDim.x + threadIdx.x;
    if (idx >= BT * 1024) return;
    int bt = idx >> 10, hw = idx & 1023;
    const float* dp = d1 + (size_t)bt * 8 * 1024 + hw;
    float l0 = ob[0], l1 = ob[1];
    #pragma unroll
    for (int c = 0; c < 8; c++) {
        float v = dp[(size_t)c << 10];
        l0 = fmaf(v, ow[c], l0);
        l1 = fmaf(v, ow[8 + c], l1);
    }
    float mx = fmaxf(fmaxf(l0, l1), 1.0f);
    float e0 = expf(l0 - mx), e1 = expf(l1 - mx), e2 = expf(1.0f - mx);
    float inv = 1.0f / (e0 + e1 + e2);
    float m0 = e0 * inv, m1 = e1 * inv;

    const float* xp = xt + (size_t)bt * 3 * 1024 + hw;
    float* fp = feat + (size_t)bt * FEAT + hw;
    #pragma unroll
    for (int c = 0; c < 3; c++) {
        float xv = xp[(size_t)c << 10];
        fp[(size_t)c << 10]       = m0 * xv;
        fp[(size_t)(3 + c) << 10] = m1 * xv;
    }
}

// -------------------- GEMM1: split-K, BM256/BN64/BK16, TM16/TN4 --------------
__global__ void __launch_bounds__(256)
sgemm1_k(const float* __restrict__ A, const float* __restrict__ Bm,
         float* __restrict__ Cpart)
{
    constexpr int M = BT, N = HID, K = FEAT;
    constexpr int BM = 256, BN = 64, BK = 16;
    constexpr int KS = K / SPLITS;  // 768
    __shared__ float sA[BK][BM + 4];
    __shared__ float sB[BK][BN + 4];

    const int tid = threadIdx.x;
    const int tx = tid % 16;
    const int ty = tid / 16;
    const int bm = blockIdx.y * BM;
    const int bn = blockIdx.x * BN;
    const int kbase = blockIdx.z * KS;

    const int c4 = tid % 4;
    const int r0 = tid / 4;

    float acc[16][4];
    #pragma unroll
    for (int i = 0; i < 16; i++)
        #pragma unroll
        for (int j = 0; j < 4; j++) acc[i][j] = 0.f;

    for (int k0 = kbase; k0 < kbase + KS; k0 += BK) {
        #pragma unroll
        for (int q = 0; q < 4; q++) {
            int rr = r0 + 64 * q;
            float4 av = *reinterpret_cast<const float4*>(&A[(size_t)(bm + rr) * K + k0 + c4 * 4]);
            sA[c4 * 4 + 0][rr] = av.x;
            sA[c4 * 4 + 1][rr] = av.y;
            sA[c4 * 4 + 2][rr] = av.z;
            sA[c4 * 4 + 3][rr] = av.w;
        }
        {
            int kk = tid / 16;
            int cc = (tid % 16) * 4;
            int gcol = bn + cc;
            float4 bv;
            if (gcol + 3 < N) {
                bv = *reinterpret_cast<const float4*>(&Bm[(size_t)(k0 + kk) * N + gcol]);
            } else {
                bv.x = (gcol + 0 < N) ? Bm[(size_t)(k0 + kk) * N + gcol + 0] : 0.f;
                bv.y = (gcol + 1 < N) ? Bm[(size_t)(k0 + kk) * N + gcol + 1] : 0.f;
                bv.z = (gcol + 2 < N) ? Bm[(size_t)(k0 + kk) * N + gcol + 2] : 0.f;
                bv.w = (gcol + 3 < N) ? Bm[(size_t)(k0 + kk) * N + gcol + 3] : 0.f;
            }
            *reinterpret_cast<float4*>(&sB[kk][cc]) = bv;
        }
        __syncthreads();

        #pragma unroll
        for (int kk = 0; kk < BK; kk++) {
            float4 b = *reinterpret_cast<const float4*>(&sB[kk][tx * 4]);
            #pragma unroll
            for (int q = 0; q < 4; q++) {
                float4 a = *reinterpret_cast<const float4*>(&sA[kk][ty * 16 + q * 4]);
                acc[q * 4 + 0][0] = fmaf(a.x, b.x, acc[q * 4 + 0][0]);
                acc[q * 4 + 0][1] = fmaf(a.x, b.y, acc[q * 4 + 0][1]);
                acc[q * 4 + 0][2] = fmaf(a.x, b.z, acc[q * 4 + 0][2]);
                acc[q * 4 + 0][3] = fmaf(a.x, b.w, acc[q * 4 + 0][3]);
                acc[q * 4 + 1][0] = fmaf(a.y, b.x, acc[q * 4 + 1][0]);
                acc[q * 4 + 1][1] = fmaf(a.y, b.y, acc[q * 4 + 1][1]);
                acc[q * 4 + 1][2] = fmaf(a.y, b.z, acc[q * 4 + 1][2]);
                acc[q * 4 + 1][3] = fmaf(a.y, b.w, acc[q * 4 + 1][3]);
                acc[q * 4 + 2][0] = fmaf(a.z, b.x, acc[q * 4 + 2][0]);
                acc[q * 4 + 2][1] = fmaf(a.z, b.y, acc[q * 4 + 2][1]);
                acc[q * 4 + 2][2] = fmaf(a.z, b.z, acc[q * 4 + 2][2]);
                acc[q * 4 + 2][3] = fmaf(a.z, b.w, acc[q * 4 + 2][3]);
                acc[q * 4 + 3][0] = fmaf(a.w, b.x, acc[q * 4 + 3][0]);
                acc[q * 4 + 3][1] = fmaf(a.w, b.y, acc[q * 4 + 3][1]);
                acc[q * 4 + 3][2] = fmaf(a.w, b.z, acc[q * 4 + 3][2]);
                acc[q * 4 + 3][3] = fmaf(a.w, b.w, acc[q * 4 + 3][3]);
            }
        }
        __syncthreads();
    }

    float* Cp = Cpart + (size_t)blockIdx.z * M * N;
    #pragma unroll
    for (int i = 0; i < 16; i++) {
        int m = bm + ty * 16 + i;
        #pragma unroll
        for (int j = 0; j < 4; j++) {
            int n = bn + tx * 4 + j;
            if (n < N) Cp[(size_t)m * N + n] = acc[i][j];
        }
    }
}

__global__ void reduce8_relu_kernel(const float* __restrict__ part,
                                    const float* __restrict__ bias,
                                    float* __restrict__ out)
{
    int idx = blockIdx.x * blockDim.x + threadIdx.x;
    if (idx >= BT * HID) return;
    int n = idx % HID;
    float v = bias[n];
    #pragma unroll
    for (int s = 0; s < SPLITS; s++) v += part[(size_t)s * BT * HID + idx];
    out[idx] = fmaxf(v, 0.f);
}

// -------------------- tiled SGEMM (GEMM2, bias+relu) --------------------------
template<int BM, int BN, int BK, int TM, int TN, bool RELU>
__global__ void sgemm_k(int M, int N, int K,
                        const float* __restrict__ A, const float* __restrict__ Bm,
                        const float* __restrict__ bias, float* __restrict__ C)
{
    __shared__ float sA[BK][BM + 1];
    __shared__ float sB[BK][BN];
    const int tid = threadIdx.x;
    const int tx = tid % (BN / TN);
    const int ty = tid / (BN / TN);
    const int bm = blockIdx.y * BM;
    const int bn = blockIdx.x * BN;

    float acc[TM][TN];
    #pragma unroll
    for (int i = 0; i < TM; i++)
        #pragma unroll
        for (int j = 0; j < TN; j++) acc[i][j] = 0.f;

    for (int k0 = 0; k0 < K; k0 += BK) {
        for (int i = tid; i < BM * BK; i += 256) {
            int m = i / BK, kk = i % BK;
            sA[kk][m] = (bm + m < M && k0 + kk < K) ? A[(size_t)(bm + m) * K + k0 + kk] : 0.f;
        }
        for (int i = tid; i < BK * BN; i += 256) {
            int kk = i / BN, n = i % BN;
            sB[kk][n] = (k0 + kk < K && bn + n < N) ? Bm[(size_t)(k0 + kk) * N + bn + n] : 0.f;
        }
        __syncthreads();
        #pragma unroll
        for (int kk = 0; kk < BK; kk++) {
            float a[TM], b[TN];
            #pragma unroll
            for (int i = 0; i < TM; i++) a[i] = sA[kk][ty * TM + i];
            #pragma unroll
            for (int j = 0; j < TN; j++) b[j] = sB[kk][tx * TN + j];
            #pragma unroll
            for (int i = 0; i < TM; i++)
                #pragma unroll
                for (int j = 0; j < TN; j++) acc[i][j] = fmaf(a[i], b[j], acc[i][j]);
        }
        __syncthreads();
    }

    #pragma unroll
    for (int i = 0; i < TM; i++) {
        int m = bm + ty * TM + i;
        if (m >= M) continue;
        #pragma unroll
        for (int j = 0; j < TN; j++) {
            int n = bn + tx * TN + j;
            if (n >= N) continue;
            float v = acc[i][j] + bias[n];
            if (RELU) v = fmaxf(v, 0.f);
            C[(size_t)m * N + n] = v;
        }
    }
}

// -------------------- final 200->4 + tanh scale ------------------------------
__global__ void loc3_kernel(const float* __restrict__ h2, const float* __restrict__ w3,
                            const float* __restrict__ b3, float* __restrict__ out)
{
    int idx = blockIdx.x * blockDim.x + threadIdx.x;
    if (idx >= BT * 4) return;
    int m = idx >> 2, j = idx & 3;
    float acc = b3[j];
    const float* hp = h2 + (size_t)m * HID;
    #pragma unroll 8
    for (int k = 0; k < HID; k++) acc = fmaf(hp[k], w3[k * 4 + j], acc);
    out[idx] = tanhf(acc) * 16.f + 16.f;
}

// -------------------- launch --------------------------------------------------
extern "C" void kernel_launch(void* const* d_in, const int* in_sizes, int n_in,
                              void* d_out, int out_size)
{
    const float* x   = (const float*)d_in[0];
    const float* ew1 = (const float*)d_in[1];
    const float* eb1 = (const float*)d_in[2];
    const float* ew2 = (const float*)d_in[3];
    const float* eb2 = (const float*)d_in[4];
    const float* ew3 = (const float*)d_in[5];
    const float* eb3 = (const float*)d_in[6];
    const float* dw2 = (const float*)d_in[7];
    const float* db2 = (const float*)d_in[8];
    const float* dw1 = (const float*)d_in[9];
    const float* db1 = (const float*)d_in[10];
    const float* ow  = (const float*)d_in[11];
    const float* ob  = (const float*)d_in[12];
    const float* lw1 = (const float*)d_in[13];
    const float* lb1 = (const float*)d_in[14];
    const float* lw2 = (const float*)d_in[15];
    const float* lb2 = (const float*)d_in[16];
    const float* lw3 = (const float*)d_in[17];
    const float* lb3 = (const float*)d_in[18];
    float* out = (float*)d_out;

    float *xt, *e1, *e2, *e3, *d2v, *d1v, *feat, *h1, *h2, *part;
    cudaGetSymbolAddress((void**)&xt,   g_xt);
    cudaGetSymbolAddress((void**)&e1,   g_e1);
    cudaGetSymbolAddress((void**)&e2,   g_e2);
    cudaGetSymbolAddress((void**)&e3,   g_e3);
    cudaGetSymbolAddress((void**)&d2v,  g_d2);
    cudaGetSymbolAddress((void**)&d1v,  g_d1);
    cudaGetSymbolAddress((void**)&feat, g_feat);
    cudaGetSymbolAddress((void**)&h1,   g_h1);
    cudaGetSymbolAddress((void**)&h2,   g_h2);
    cudaGetSymbolAddress((void**)&part, g_part);

    // smem bytes (padded layouts, R3-proven)
    constexpr int SM_E1 = (3 * 8 * 9  + 8  + 2 * 3 * 32 * 33) * 4;                    // 26240
    constexpr int SM_E2 = (8 * 16 * 9 + 16 + 4 * 8 * 16 * 17) * 4;                    // 39488
    constexpr int SM_E3 = (16 * 32 * 9 + 32 + 8 * 16 * 8 * 9) * 4;                    // 55424
    constexpr int SM_D2 = (48 * 16 * 9 + 16 + 2 * (32 * 8 * 9 + 16 * 16 * 17)) * 4;   // 80960
    constexpr int SM_D1 = (24 * 8 * 9 + 8 + 2 * (16 * 16 * 17 + 8 * 32 * 33)) * 4;    // 109344

    cudaFuncSetAttribute((const void*)conv_std_k<8, 16, 8, 16, 4, 8, true>,
                         cudaFuncAttributeMaxDynamicSharedMemorySize, SM_E2);
    cudaFuncSetAttribute((const void*)conv_std_k<16, 32, 8, 8, 8, 8, true>,
                         cudaFuncAttributeMaxDynamicSharedMemorySize, SM_E3);
    cudaFuncSetAttribute((const void*)conv_up_k<32, 16, 16, 4, 16, 2, 8>,
                         cudaFuncAttributeMaxDynamicSharedMemorySize, SM_D2);
    cudaFuncSetAttribute((const void*)conv_up_k<16, 8, 8, 8, 32, 2, 8>,
                         cudaFuncAttributeMaxDynamicSharedMemorySize, SM_D1);

    // 1) permute
    permute_kernel<<<32 * 3 * 32, 256>>>(x, xt);
    // 2) e1 = relu(conv 3->8 @32)
    conv_std_k<3, 8, 8, 32, 2, 8, false><<<BT / 2, 256, SM_E1>>>(xt, ew1, eb1, e1);
    // 3) e2 = relu(conv pool(e1) 8->16 @16)
    conv_std_k<8, 16, 8, 16, 4, 8, true><<<BT / 4, 256, SM_E2>>>(e1, ew2, eb2, e2);
    // 4) e3 = relu(conv pool(e2) 16->32 @8)
    conv_std_k<16, 32, 8, 8, 8, 8, true><<<BT / 8, 256, SM_E3>>>(e2, ew3, eb3, e3);
    // 5) d2 = relu(conv [up(e3), e2] 48->16 @16)
    conv_up_k<32, 16, 16, 4, 16, 2, 8><<<BT / 2, 256, SM_D2>>>(e3, e2, dw2, db2, d2v);
    // 6) d1 = relu(conv [up(d2), e1] 24->8 @32)
    conv_up_k<16, 8, 8, 8, 32, 2, 8><<<BT / 2, 256, SM_D1>>>(d2v, e1, dw1, db1, d1v);
    // 7) masks + masked features
    mask_feat_kernel<<<(BT * 1024) / 256, 256>>>(d1v, xt, ow, ob, feat);
    // 8) h1 = relu(feat @ lw1 + lb1) via split-K x8
    sgemm1_k<<<dim3(4, BT / 256, SPLITS), 256>>>(feat, lw1, part);
    reduce8_relu_kernel<<<(BT * HID + 255) / 256, 256>>>(part, lb1, h1);
    // 9) h2 = relu(h1 @ lw2 + lb2)
    sgemm_k<64, 64, 16, 4, 4, true><<<dim3(4, BT / 64), 256>>>(BT, HID, HID, h1, lw2, lb2, h2);
    // 10) out = tanh(h2 @ lw3 + lb3)*16+16
    loc3_kernel<<<(BT * 4 + 255) / 256, 256>>>(h2, lw3, lb3, out);
}